// round 14
// baseline (speedup 1.0000x reference)
#include <cuda_runtime.h>
#include <cuda_fp16.h>
#include <cstdint>

#define BATCH  8192
#define SEQ    100
#define EMBED  50
#define HID    20
#define NLABEL 15
#define VOCAB  50000

// Precomputed P[v][64] = rearranged(emb_table[v] @ W1 + bi1), owner-major:
// owner q (0..3) gets 16 slots: [0..4]=z cols q*5.., [5..9]=r, [10..14]=h, [15]=pad
__device__ float g_P[VOCAB * 64];

// ---------------- helpers ----------------
__device__ __forceinline__ unsigned long long fma2(unsigned long long a,
                                                   unsigned long long b,
                                                   unsigned long long c) {
    unsigned long long d;
    asm("fma.rn.f32x2 %0, %1, %2, %3;" : "=l"(d) : "l"(a), "l"(b), "l"(c));
    return d;
}
__device__ __forceinline__ unsigned long long pack2(float f) {
    unsigned long long r;
    unsigned int u = __float_as_uint(f);
    asm("mov.b64 %0, {%1, %1};" : "=l"(r) : "r"(u));
    return r;
}
__device__ __forceinline__ float2 unpack2(unsigned long long v) {
    float2 r;
    asm("mov.b64 {%0, %1}, %2;" : "=f"(r.x), "=f"(r.y) : "l"(v));
    return r;
}
// half2 (packed in u32) -> packed f32x2 in u64
__device__ __forceinline__ unsigned long long h2f2(unsigned int h) {
    unsigned long long r;
    asm("{\n\t"
        ".reg .b16 lo, hi;\n\t"
        ".reg .f32 flo, fhi;\n\t"
        "mov.b32 {lo, hi}, %1;\n\t"
        "cvt.f32.f16 flo, lo;\n\t"
        "cvt.f32.f16 fhi, hi;\n\t"
        "mov.b64 %0, {flo, fhi};\n\t"
        "}" : "=l"(r) : "r"(h));
    return r;
}
__device__ __forceinline__ float tanha(float x) {
    float y;
    asm("tanh.approx.f32 %0, %1;" : "=f"(y) : "f"(x));
    return y;
}
// rearranged slot index (0..63) -> original gate column (0..59), or -1 pad
__device__ __forceinline__ int remap_col(int j64) {
    int q = j64 >> 4;
    int jj = j64 & 15;
    if (jj >= 15) return -1;
    int g = jj / 5;
    int l = jj - g * 5;
    return g * HID + q * 5 + l;
}

// ---------------- P precompute ----------------
#define VPB 64
__global__ void __launch_bounds__(256) prep_P_kernel(const float* __restrict__ emb,
                                                     const float* __restrict__ W1,
                                                     const float* __restrict__ b1) {
    __shared__ __align__(16) float W1r[EMBED][64];
    __shared__ float biasr[64];
    __shared__ float embs[VPB][EMBED];
    int tid = threadIdx.x;
    for (int d = tid; d < EMBED * 64; d += 256) {
        int k = d >> 6, j = d & 63;
        int src = remap_col(j);
        W1r[k][j] = (src >= 0) ? W1[k * (3 * HID) + src] : 0.0f;
    }
    if (tid < 64) {
        int src = remap_col(tid);
        biasr[tid] = (src >= 0) ? b1[src] : 0.0f;
    }
    int v0 = blockIdx.x * VPB;
    for (int i = tid; i < VPB * EMBED; i += 256) {
        int vv = i / EMBED, k = i - vv * EMBED;
        int v = v0 + vv;
        embs[vv][k] = (v < VOCAB) ? emb[v * EMBED + k] : 0.0f;
    }
    __syncthreads();
    int d = tid & 63;
    int vbase = tid >> 6;
    #pragma unroll
    for (int i = 0; i < 16; i++) {
        int vl = vbase + 4 * i;
        int v = v0 + vl;
        if (v >= VOCAB) continue;
        float acc = biasr[d];
        #pragma unroll
        for (int k = 0; k < EMBED; k++)
            acc = fmaf(embs[vl][k], W1r[k][d], acc);
        g_P[v * 64 + d] = acc;
    }
}

// ---------------- main fused GRU kernel ----------------
// Matrix-split: 12 threads per row-pair = (q owner 0..3) x (m matrix 0..2),
// 2 rows per thread.  m=0: U1*h1 (+GRU1 gates, px gather, h1 writeback);
// m=1: W2*h1 (+GRU2 gates via exchange, h2 writeback); m=2: U2*h2 (-> smem
// exchange).  Weight bytes per row unchanged vs R13; warps/SM tripled.
// sW (halves): [k][mat][s64], k-stride 240 halves (60 uint2), mat-stride 80
// halves (20 uint2, padded so (m,q) lanes land on distinct bank pairs).
#define RPB     56
#define PAIRS   28
#define BLOCK   336         // 28 pairs * 12
#define HSTRIDE 21
#define EXQ     9           // u64 per (row,q) exchange slot (padded from 8)
#define EXROW   (4 * EXQ)   // 36 u64 per row
#define EXPAIR  (2 * EXROW) // 72 u64 per pair

__global__ void __launch_bounds__(BLOCK) gru_main_kernel(
    const int*   __restrict__ x,
    const float* __restrict__ U1,
    const float* __restrict__ b1,
    const float* __restrict__ W2,
    const float* __restrict__ U2,
    const float* __restrict__ b2,
    const float* __restrict__ Wd,
    const float* __restrict__ bd,
    float*       __restrict__ out) {

    __shared__ __align__(16) __half sW[HID * 240];            // 9600 B
    __shared__ __align__(16) unsigned long long sEx[PAIRS * EXPAIR]; // 16128 B
    __shared__ __align__(16) float sbr1[64];
    __shared__ __align__(16) float sbi2[64];
    __shared__ __align__(16) float sbr2[64];
    __shared__ __align__(16) float sWd[HID * 16];
    __shared__ float sbd[16];
    __shared__ __align__(16) float sh1[RPB * HSTRIDE];
    __shared__ __align__(16) float sh2[RPB * HSTRIDE];

    int tid = threadIdx.x;

    // ---- stage weights fp16, layout [k][mat][s64] with mat-stride 80 ----
    for (int d = tid; d < HID * 240; d += BLOCK) {
        int k   = d / 240;
        int rem = d - k * 240;
        int mat = rem / 80;
        int s64 = rem - mat * 80;          // 0..79; >=64 is pad
        float v = 0.0f;
        if (s64 < 64) {
            int j  = s64 >> 4;
            int q_ = (s64 >> 2) & 3;
            int c  = s64 & 3;
            int src = remap_col(q_ * 16 + (j * 4 + c));
            if (src >= 0) {
                int idx = k * (3 * HID) + src;
                v = (mat == 0) ? U1[idx] : (mat == 1) ? W2[idx] : U2[idx];
            }
        }
        sW[d] = __float2half(v);
    }
    if (tid < 64) {
        int src = remap_col(tid);
        float a = 0.0f, bb = 0.0f, c = 0.0f;
        if (src >= 0) {
            a  = b1[3 * HID + src];
            bb = b2[src];
            c  = b2[3 * HID + src];
        }
        sbr1[tid] = a; sbi2[tid] = bb; sbr2[tid] = c;
    }
    for (int d = tid; d < HID * 16; d += BLOCK) {
        int k = d >> 4, j = d & 15;
        sWd[d] = (j < NLABEL) ? Wd[k * NLABEL + j] : 0.0f;
    }
    if (tid < 16) sbd[tid] = (tid < NLABEL) ? bd[tid] : 0.0f;

    int pair = tid / 12;
    int mq   = tid - pair * 12;
    int m    = mq >> 2;          // matrix 0..2
    int q    = mq & 3;           // owner

    int rowa_orig = blockIdx.x * RPB + pair * 2;
    int rowa = (rowa_orig <= BATCH - 2) ? rowa_orig : (BATCH - 2);

    float* ph1a = sh1 + (pair * 2) * HSTRIDE;
    float* ph1b = ph1a + HSTRIDE;
    float* ph2a = sh2 + (pair * 2) * HSTRIDE;
    float* ph2b = ph2a + HSTRIDE;

    const int* xa = x + (size_t)rowa * SEQ;
    const int* xb = xa + SEQ;

    // m-parametrized pointers
    const uint2* wbase = reinterpret_cast<const uint2*>(sW) + m * 20;  // +k*60
    const float* hA = (m == 2) ? ph2a : ph1a;
    const float* hB = (m == 2) ? ph2b : ph1b;
    const float* sbias = (m == 0) ? sbr1 : (m == 1) ? sbi2 : sbr2;
    const ulonglong2* biasv = reinterpret_cast<const ulonglong2*>(sbias) + q * 4;
    unsigned long long* exa = sEx + pair * EXPAIR + q * EXQ;
    unsigned long long* exb = exa + EXROW;

    float h1oa[5], h1ob[5], h2oa[5], h2ob[5];
    #pragma unroll
    for (int i = 0; i < 5; i++) {
        h1oa[i] = 0.f; h1ob[i] = 0.f; h2oa[i] = 0.f; h2ob[i] = 0.f;
    }
    if (m == 1) {
        #pragma unroll
        for (int i = 0; i < 5; i++) { ph2a[q * 5 + i] = 0.f; ph2b[q * 5 + i] = 0.f; }
    }

    int tok_na = 0, tok_nb = 0;

    // -------- prologue: GRU1(0) (m==0; h1=0 -> recurrent side = br1) ------
    if (m == 0) {
        int toka = xa[0], tokb = xb[0];
        const float4* ppa = reinterpret_cast<const float4*>(g_P + (size_t)toka * 64 + q * 16);
        const float4* ppb = reinterpret_cast<const float4*>(g_P + (size_t)tokb * 64 + q * 16);
        float4 a0 = ppa[0], a1 = ppa[1], a2 = ppa[2], a3 = ppa[3];
        float4 b0 = ppb[0], b1_ = ppb[1], b2_ = ppb[2], b3 = ppb[3];
        float pxa[16] = {a0.x,a0.y,a0.z,a0.w, a1.x,a1.y,a1.z,a1.w,
                         a2.x,a2.y,a2.z,a2.w, a3.x,a3.y,a3.z,a3.w};
        float pxb[16] = {b0.x,b0.y,b0.z,b0.w, b1_.x,b1_.y,b1_.z,b1_.w,
                         b2_.x,b2_.y,b2_.z,b2_.w, b3.x,b3.y,b3.z,b3.w};
        #pragma unroll
        for (int i = 0; i < 5; i++) {
            float c0 = sbr1[q * 16 + i];
            float c1 = sbr1[q * 16 + 5 + i];
            float c2 = sbr1[q * 16 + 10 + i];
            {
                float zt = tanha(0.5f * (pxa[i] + c0));
                float r  = 0.5f + 0.5f * tanha(0.5f * (pxa[5 + i] + c1));
                float hh = tanha(pxa[10 + i] + r * c2);
                h1oa[i] = 0.5f * hh - 0.5f * zt * hh;
            }
            {
                float zt = tanha(0.5f * (pxb[i] + c0));
                float r  = 0.5f + 0.5f * tanha(0.5f * (pxb[5 + i] + c1));
                float hh = tanha(pxb[10 + i] + r * c2);
                h1ob[i] = 0.5f * hh - 0.5f * zt * hh;
            }
            ph1a[q * 5 + i] = h1oa[i];
            ph1b[q * 5 + i] = h1ob[i];
        }
        tok_na = xa[1];
        tok_nb = xb[1];
    }
    __syncthreads();

    // -------- main loop: iteration t does GRU2(t) and GRU1(t+1) --------
    for (int t = 0; t < SEQ - 1; t++) {
        float pxa[16], pxb[16];
        if (m == 0) {   // prefetch input projections for GRU1(t+1)
            const float4* ppa = reinterpret_cast<const float4*>(g_P + (size_t)tok_na * 64 + q * 16);
            const float4* ppb = reinterpret_cast<const float4*>(g_P + (size_t)tok_nb * 64 + q * 16);
            float4 a0 = ppa[0], a1 = ppa[1], a2 = ppa[2], a3 = ppa[3];
            float4 b0 = ppb[0], b1_ = ppb[1], b2_ = ppb[2], b3 = ppb[3];
            pxa[0]=a0.x;pxa[1]=a0.y;pxa[2]=a0.z;pxa[3]=a0.w;
            pxa[4]=a1.x;pxa[5]=a1.y;pxa[6]=a1.z;pxa[7]=a1.w;
            pxa[8]=a2.x;pxa[9]=a2.y;pxa[10]=a2.z;pxa[11]=a2.w;
            pxa[12]=a3.x;pxa[13]=a3.y;pxa[14]=a3.z;pxa[15]=a3.w;
            pxb[0]=b0.x;pxb[1]=b0.y;pxb[2]=b0.z;pxb[3]=b0.w;
            pxb[4]=b1_.x;pxb[5]=b1_.y;pxb[6]=b1_.z;pxb[7]=b1_.w;
            pxb[8]=b2_.x;pxb[9]=b2_.y;pxb[10]=b2_.z;pxb[11]=b2_.w;
            pxb[12]=b3.x;pxb[13]=b3.y;pxb[14]=b3.z;pxb[15]=b3.w;
            int t2 = t + 2;
            int i2 = (t2 < SEQ) ? t2 : (SEQ - 1);
            tok_na = xa[i2];
            tok_nb = xb[i2];
        }

        // ---- my matrix's matvec for both rows ----
        unsigned long long Ra[8], Rb[8];
        #pragma unroll
        for (int j = 0; j < 4; j++) {
            ulonglong2 tb = biasv[j];
            Ra[2*j] = tb.x; Ra[2*j+1] = tb.y;
            Rb[2*j] = tb.x; Rb[2*j+1] = tb.y;
        }
        #pragma unroll 5
        for (int k = 0; k < HID; k++) {
            unsigned long long hap = pack2(hA[k]);
            unsigned long long hbp = pack2(hB[k]);
            const uint2* wk = wbase + k * 60;
            #pragma unroll
            for (int j = 0; j < 4; j++) {
                uint2 w = wk[j * 4 + q];
                unsigned long long W0 = h2f2(w.x), W1 = h2f2(w.y);
                Ra[2*j]   = fma2(W0, hap, Ra[2*j]);
                Ra[2*j+1] = fma2(W1, hap, Ra[2*j+1]);
                Rb[2*j]   = fma2(W0, hbp, Rb[2*j]);
                Rb[2*j+1] = fma2(W1, hbp, Rb[2*j+1]);
            }
        }

        if (m == 2) {     // ship U2*h2 preacts to m==1
            #pragma unroll
            for (int j = 0; j < 8; j++) { exa[j] = Ra[j]; exb[j] = Rb[j]; }
        }
        if (m == 0) {     // GRU1(t+1) gates
            float aa[16], ab[16];
            #pragma unroll
            for (int j = 0; j < 8; j++) {
                float2 fa = unpack2(Ra[j]); aa[2*j] = fa.x; aa[2*j+1] = fa.y;
                float2 fb = unpack2(Rb[j]); ab[2*j] = fb.x; ab[2*j+1] = fb.y;
            }
            #pragma unroll
            for (int i = 0; i < 5; i++) {
                float zt = tanha(0.5f * (pxa[i] + aa[i]));
                float r  = 0.5f + 0.5f * tanha(0.5f * (pxa[5+i] + aa[5+i]));
                float hh = tanha(pxa[10+i] + r * aa[10+i]);
                float ho = h1oa[i];
                h1oa[i] = 0.5f * (ho + hh) + 0.5f * zt * (ho - hh);
            }
            #pragma unroll
            for (int i = 0; i < 5; i++) {
                float zt = tanha(0.5f * (pxb[i] + ab[i]));
                float r  = 0.5f + 0.5f * tanha(0.5f * (pxb[5+i] + ab[5+i]));
                float hh = tanha(pxb[10+i] + r * ab[10+i]);
                float ho = h1ob[i];
                h1ob[i] = 0.5f * (ho + hh) + 0.5f * zt * (ho - hh);
            }
        }
        __syncthreads();   // exchange visible; all old-h reads done

        if (m == 0) {      // publish h1(t+1)
            #pragma unroll
            for (int i = 0; i < 5; i++) {
                ph1a[q * 5 + i] = h1oa[i];
                ph1b[q * 5 + i] = h1ob[i];
            }
        }
        if (m == 1) {      // GRU2(t) gates: X (mine) + H (from m==2)
            float bxa[16], bxb[16], bha[16], bhb[16];
            #pragma unroll
            for (int j = 0; j < 8; j++) {
                float2 fx = unpack2(Ra[j]); bxa[2*j] = fx.x; bxa[2*j+1] = fx.y;
                float2 fy = unpack2(Rb[j]); bxb[2*j] = fy.x; bxb[2*j+1] = fy.y;
                float2 fh = unpack2(exa[j]); bha[2*j] = fh.x; bha[2*j+1] = fh.y;
                float2 fg = unpack2(exb[j]); bhb[2*j] = fg.x; bhb[2*j+1] = fg.y;
            }
            #pragma unroll
            for (int i = 0; i < 5; i++) {
                float zt = tanha(0.5f * (bxa[i] + bha[i]));
                float r  = 0.5f + 0.5f * tanha(0.5f * (bxa[5+i] + bha[5+i]));
                float hh = tanha(bxa[10+i] + r * bha[10+i]);
                float ho = h2oa[i];
                h2oa[i] = 0.5f * (ho + hh) + 0.5f * zt * (ho - hh);
            }
            #pragma unroll
            for (int i = 0; i < 5; i++) {
                float zt = tanha(0.5f * (bxb[i] + bhb[i]));
                float r  = 0.5f + 0.5f * tanha(0.5f * (bxb[5+i] + bhb[5+i]));
                float hh = tanha(bxb[10+i] + r * bhb[10+i]);
                float ho = h2ob[i];
                h2ob[i] = 0.5f * (ho + hh) + 0.5f * zt * (ho - hh);
            }
            #pragma unroll
            for (int i = 0; i < 5; i++) {
                ph2a[q * 5 + i] = h2oa[i];
                ph2b[q * 5 + i] = h2ob[i];
            }
        }
        __syncthreads();   // new h visible
    }

    // -------- epilogue: GRU2(SEQ-1) --------
    {
        unsigned long long Ra[8], Rb[8];
        #pragma unroll
        for (int j = 0; j < 4; j++) {
            ulonglong2 tb = biasv[j];
            Ra[2*j] = tb.x; Ra[2*j+1] = tb.y;
            Rb[2*j] = tb.x; Rb[2*j+1] = tb.y;
        }
        #pragma unroll 5
        for (int k = 0; k < HID; k++) {
            unsigned long long hap = pack2(hA[k]);
            unsigned long long hbp = pack2(hB[k]);
            const uint2* wk = wbase + k * 60;
            #pragma unroll
            for (int j = 0; j < 4; j++) {
                uint2 w = wk[j * 4 + q];
                unsigned long long W0 = h2f2(w.x), W1 = h2f2(w.y);
                Ra[2*j]   = fma2(W0, hap, Ra[2*j]);
                Ra[2*j+1] = fma2(W1, hap, Ra[2*j+1]);
                Rb[2*j]   = fma2(W0, hbp, Rb[2*j]);
                Rb[2*j+1] = fma2(W1, hbp, Rb[2*j+1]);
            }
        }
        if (m == 2) {
            #pragma unroll
            for (int j = 0; j < 8; j++) { exa[j] = Ra[j]; exb[j] = Rb[j]; }
        }
        __syncthreads();
        if (m == 1) {
            float bxa[16], bxb[16], bha[16], bhb[16];
            #pragma unroll
            for (int j = 0; j < 8; j++) {
                float2 fx = unpack2(Ra[j]); bxa[2*j] = fx.x; bxa[2*j+1] = fx.y;
                float2 fy = unpack2(Rb[j]); bxb[2*j] = fy.x; bxb[2*j+1] = fy.y;
                float2 fh = unpack2(exa[j]); bha[2*j] = fh.x; bha[2*j+1] = fh.y;
                float2 fg = unpack2(exb[j]); bhb[2*j] = fg.x; bhb[2*j+1] = fg.y;
            }
            #pragma unroll
            for (int i = 0; i < 5; i++) {
                float zt = tanha(0.5f * (bxa[i] + bha[i]));
                float r  = 0.5f + 0.5f * tanha(0.5f * (bxa[5+i] + bha[5+i]));
                float hh = tanha(bxa[10+i] + r * bha[10+i]);
                float ho = h2oa[i];
                h2oa[i] = 0.5f * (ho + hh) + 0.5f * zt * (ho - hh);
            }
            #pragma unroll
            for (int i = 0; i < 5; i++) {
                float zt = tanha(0.5f * (bxb[i] + bhb[i]));
                float r  = 0.5f + 0.5f * tanha(0.5f * (bxb[5+i] + bhb[5+i]));
                float hh = tanha(bxb[10+i] + r * bhb[10+i]);
                float ho = h2ob[i];
                h2ob[i] = 0.5f * (ho + hh) + 0.5f * zt * (ho - hh);
            }
            #pragma unroll
            for (int i = 0; i < 5; i++) {
                ph2a[q * 5 + i] = h2oa[i];
                ph2b[q * 5 + i] = h2ob[i];
            }
        }
        __syncthreads();
    }

    // -------- dense head (m==0 threads; cols q*4..q*4+3, rows a,b) --------
    if (m == 0 && rowa_orig < BATCH) {
        float hva[HID], hvb[HID];
        #pragma unroll
        for (int k = 0; k < HID; k++) { hva[k] = ph2a[k]; hvb[k] = ph2b[k]; }
        #pragma unroll
        for (int c = 0; c < 4; c++) {
            int col = q * 4 + c;
            if (col >= NLABEL) break;
            float da = sbd[col], db = sbd[col];
            #pragma unroll
            for (int k = 0; k < HID; k++) {
                float w = sWd[k * 16 + col];
                da = fmaf(hva[k], w, da);
                db = fmaf(hvb[k], w, db);
            }
            out[(size_t)rowa_orig * NLABEL + col] = da;
            out[(size_t)(rowa_orig + 1) * NLABEL + col] = db;
        }
    }
}

// ---------------- launch ----------------
extern "C" void kernel_launch(void* const* d_in, const int* in_sizes, int n_in,
                              void* d_out, int out_size) {
    const int*   x    = (const int*)  d_in[0];
    const float* emb  = (const float*)d_in[1];
    const float* W1   = (const float*)d_in[2];
    const float* U1   = (const float*)d_in[3];
    const float* b1   = (const float*)d_in[4];
    const float* W2   = (const float*)d_in[5];
    const float* U2   = (const float*)d_in[6];
    const float* b2   = (const float*)d_in[7];
    const float* Wd   = (const float*)d_in[8];
    const float* bd   = (const float*)d_in[9];
    float* out = (float*)d_out;

    prep_P_kernel<<<(VOCAB + VPB - 1) / VPB, 256>>>(emb, W1, b1);
    gru_main_kernel<<<(BATCH + RPB - 1) / RPB, BLOCK>>>(x, U1, b1, W2, U2, b2, Wd, bd, out);
}